// round 16
// baseline (speedup 1.0000x reference)
#include <cuda_runtime.h>
#include <math.h>
#include <stdint.h>

// Problem constants (fixed by reference)
#define BB 256
#define TT 72
#define NN 5
#define FF_IN 10
#define HH 4
#define CC 32
#define DD 128
#define FFD 256
#define NHEAD 4
#define DHEAD 32
#define BT (BB*TT)   // 18432

// ---------------- device scratch (no allocations allowed) ----------------
__device__ float    d_z[BT*DD];
__device__ float    d_qkv[BT*3*DD];
__device__ uint32_t d_ztf[BT*DD];
__device__ uint32_t d_otf[BT*DD];
__device__ uint32_t d_fftf[BT*FFD];
__device__ float    d_Anorm[NN*NN];
__device__ int      d_src2[64];
__device__ int      d_dst2[64];
__device__ int      d_rowptr[NN+1];

// pre-converted tf32 weights: [qkv | o | ff1 | ff2]
#define WOFF_QKV 0
#define WOFF_O   (3*DD*3*DD)
#define WOFF_FF1 (WOFF_O + 3*DD*DD)
#define WOFF_FF2 (WOFF_FF1 + 3*DD*FFD)
#define WTF_TOTAL (WOFF_FF2 + 3*FFD*DD)
__device__ uint32_t d_wtf[WTF_TOTAL];

// ---------------- tf32 helpers ----------------
__device__ __forceinline__ uint32_t to_tf32(float x) {
    uint32_t r;
    asm("cvt.rna.tf32.f32 %0, %1;" : "=r"(r) : "f"(x));
    return r;
}
__device__ __forceinline__ void mma_tf32(float* d, const uint32_t* a, const uint32_t* b) {
    asm volatile(
        "mma.sync.aligned.m16n8k8.row.col.f32.tf32.tf32.f32 "
        "{%0,%1,%2,%3}, {%4,%5,%6,%7}, {%8,%9}, {%0,%1,%2,%3};"
        : "+f"(d[0]), "+f"(d[1]), "+f"(d[2]), "+f"(d[3])
        : "r"(a[0]), "r"(a[1]), "r"(a[2]), "r"(a[3]), "r"(b[0]), "r"(b[1]));
}
__device__ __forceinline__ void cp_async16(void* smem_dst, const void* gmem_src) {
    uint32_t s = (uint32_t)__cvta_generic_to_shared(smem_dst);
    asm volatile("cp.async.ca.shared.global [%0], [%1], 16;" :: "r"(s), "l"(gmem_src));
}
__device__ __forceinline__ float fast_tanh(float x) {
    x = fminf(fmaxf(x, -15.f), 15.f);
    float e = __expf(2.f * x);
    return (e - 1.f) / (e + 1.f);
}

// ---------------- weight pre-conversion (rna, once per launch) ----------------
__global__ void cvt_weights_kernel(const float* __restrict__ qkv, const float* __restrict__ o,
                                   const float* __restrict__ ff1, const float* __restrict__ ff2)
{
    int i = blockIdx.x * blockDim.x + threadIdx.x;
    int stride = gridDim.x * blockDim.x;
    for (int idx = i; idx < 3*DD*3*DD; idx += stride) d_wtf[WOFF_QKV + idx] = to_tf32(qkv[idx]);
    for (int idx = i; idx < 3*DD*DD;   idx += stride) d_wtf[WOFF_O   + idx] = to_tf32(o[idx]);
    for (int idx = i; idx < 3*DD*FFD;  idx += stride) d_wtf[WOFF_FF1 + idx] = to_tf32(ff1[idx]);
    for (int idx = i; idx < 3*FFD*DD;  idx += stride) d_wtf[WOFF_FF2 + idx] = to_tf32(ff2[idx]);
}

// ---------------- graph build: Anorm + dst-sorted CSR ----------------
__global__ void build_graph_kernel(const int* __restrict__ ei, int E) {
    if (threadIdx.x != 0 || blockIdx.x != 0) return;
    float A[NN][NN];
    for (int i = 0; i < NN*NN; i++) ((float*)A)[i] = 0.f;
    int ts[64], td[64];
    int E2 = E + NN;
    for (int e = 0; e < E; e++) {
        int s = ei[e], d = ei[E + e];
        A[d][s] += 1.f;
        ts[e] = s; td[e] = d;
    }
    for (int n = 0; n < NN; n++) {
        A[n][n] += 1.f;
        ts[E + n] = n; td[E + n] = n;
    }
    int cnt[NN];
    for (int n = 0; n < NN; n++) cnt[n] = 0;
    for (int e = 0; e < E2; e++) cnt[td[e]]++;
    d_rowptr[0] = 0;
    for (int n = 0; n < NN; n++) d_rowptr[n+1] = d_rowptr[n] + cnt[n];
    int pos[NN];
    for (int n = 0; n < NN; n++) pos[n] = d_rowptr[n];
    for (int e = 0; e < E2; e++) {
        int p = pos[td[e]]++;
        d_src2[p] = ts[e];
        d_dst2[p] = td[e];
    }
    float dinv[NN];
    for (int n = 0; n < NN; n++) {
        float s = 0.f;
        for (int j = 0; j < NN; j++) s += A[n][j];
        dinv[n] = (s > 0.f) ? (1.f / sqrtf(s)) : 0.f;
    }
    for (int i = 0; i < NN; i++)
        for (int j = 0; j < NN; j++)
            d_Anorm[i*NN + j] = dinv[i] * A[i][j] * dinv[j];
}

// ---------------- fused GCN + GAT + LN + node-mean + PE (2 tokens/block) ----
__global__ void __launch_bounds__(256)
gcn_gat_kernel(
    const float* __restrict__ x,
    const float* __restrict__ gcn_w, const float* __restrict__ gcn_b,
    const float* __restrict__ gat_w, const float* __restrict__ a_src,
    const float* __restrict__ a_dst, const float* __restrict__ gat_b,
    const float* __restrict__ gln_g, const float* __restrict__ gln_b,
    float* __restrict__ z, uint32_t* __restrict__ ztf, int E2)
{
    int tid = threadIdx.x;          // 256
    int tok = tid >> 7;             // 0 or 1
    int ltid = tid & 127;           // local tid within token
    int bt = blockIdx.x * 2 + tok;

    __shared__ __align__(16) float sxw[2][NN][64];
    __shared__ __align__(16) float sgcn[2][NN][64];
    __shared__ __align__(16) float sh[2][NN][DD];
    __shared__ __align__(16) float sagg[2][NN][DD];
    __shared__ __align__(16) float sln[2][NN][DD];
    __shared__ float sx[2][NN][FF_IN];
    __shared__ float sas[2][NN][HH], sad[2][NN][HH];
    __shared__ float se[2][32][HH];
    __shared__ float salpha[2][32][HH];
    __shared__ float smx[2][NN][HH], sden[2][NN][HH];
    __shared__ float sAn[NN*NN];
    __shared__ int   ssrc[32], sdst[32];
    __shared__ int   srp[NN+1];

    const float* xp = x + (size_t)bt * NN * FF_IN;
    if (ltid < NN*FF_IN) ((float*)sx[tok])[ltid] = xp[ltid];
    if (tid < NN*NN) sAn[tid] = d_Anorm[tid];
    if (tid < E2) { ssrc[tid] = d_src2[tid]; sdst[tid] = d_dst2[tid]; }
    if (tid < NN+1) srp[tid] = d_rowptr[tid];
    __syncthreads();

    // xw = x @ gcn_w + gcn_b (float4)
    for (int idx = ltid; idx < NN*16; idx += 128) {
        int n = idx >> 4, c4 = (idx & 15) * 4;
        float4 acc = *(const float4*)&gcn_b[c4];
        #pragma unroll
        for (int f = 0; f < FF_IN; f++) {
            float xv = sx[tok][n][f];
            float4 w = *(const float4*)&gcn_w[f*64 + c4];
            acc.x += xv*w.x; acc.y += xv*w.y; acc.z += xv*w.z; acc.w += xv*w.w;
        }
        *(float4*)&sxw[tok][n][c4] = acc;
    }
    __syncthreads();

    // gcn = tanh(Anorm @ xw)
    for (int idx = ltid; idx < NN*16; idx += 128) {
        int n = idx >> 4, c4 = (idx & 15) * 4;
        float4 acc = make_float4(0.f, 0.f, 0.f, 0.f);
        #pragma unroll
        for (int m = 0; m < NN; m++) {
            float a = sAn[n*NN + m];
            float4 xw = *(const float4*)&sxw[tok][m][c4];
            acc.x += a*xw.x; acc.y += a*xw.y; acc.z += a*xw.z; acc.w += a*xw.w;
        }
        acc.x = fast_tanh(acc.x); acc.y = fast_tanh(acc.y);
        acc.z = fast_tanh(acc.z); acc.w = fast_tanh(acc.w);
        *(float4*)&sgcn[tok][n][c4] = acc;
    }
    __syncthreads();

    // h = gcn @ gat_w
    for (int idx = ltid; idx < NN*32; idx += 128) {
        int n = idx >> 5, d4 = (idx & 31) * 4;
        float4 acc = make_float4(0.f, 0.f, 0.f, 0.f);
        #pragma unroll 8
        for (int f = 0; f < 64; f++) {
            float g = sgcn[tok][n][f];
            float4 w = *(const float4*)&gat_w[f*DD + d4];
            acc.x += g*w.x; acc.y += g*w.y; acc.z += g*w.z; acc.w += g*w.w;
        }
        *(float4*)&sh[tok][n][d4] = acc;
    }
    __syncthreads();

    // attention coefficients
    if (ltid < NN*HH*2) {
        int n = ltid / (HH*2), r = ltid % (HH*2), hd = r >> 1, which = r & 1;
        const float* av = which ? a_dst : a_src;
        float acc = 0.f;
        #pragma unroll
        for (int c = 0; c < CC; c++) acc += sh[tok][n][hd*CC + c] * av[hd*CC + c];
        if (which) sad[tok][n][hd] = acc; else sas[tok][n][hd] = acc;
    }
    __syncthreads();

    // edge scores + leaky relu
    for (int idx = ltid; idx < E2*HH; idx += 128) {
        int e = idx >> 2, hd = idx & 3;
        float v = sas[tok][ssrc[e]][hd] + sad[tok][sdst[e]][hd];
        se[tok][e][hd] = (v > 0.f) ? v : 0.2f * v;
    }
    __syncthreads();

    // per-dst softmax stats: CSR segment scan
    if (ltid < NN*HH) {
        int n = ltid >> 2, hd = ltid & 3;
        int e0 = srp[n], e1 = srp[n+1];
        float m = -1e30f;
        for (int e = e0; e < e1; e++) m = fmaxf(m, se[tok][e][hd]);
        float s = 0.f;
        for (int e = e0; e < e1; e++) s += __expf(se[tok][e][hd] - m);
        smx[tok][n][hd] = m; sden[tok][n][hd] = s;
    }
    __syncthreads();

    for (int idx = ltid; idx < E2*HH; idx += 128) {
        int e = idx >> 2, hd = idx & 3;
        int n = sdst[e];
        salpha[tok][e][hd] = __expf(se[tok][e][hd] - smx[tok][n][hd]) / sden[tok][n][hd];
    }
    __syncthreads();

    // aggregate + gat bias : CSR segment, float4
    for (int idx = ltid; idx < NN*32; idx += 128) {
        int n = idx >> 5, d4 = (idx & 31) * 4;
        int hd = d4 >> 5;
        int e0 = srp[n], e1 = srp[n+1];
        float4 acc = make_float4(0.f, 0.f, 0.f, 0.f);
        for (int e = e0; e < e1; e++) {
            float al = salpha[tok][e][hd];
            float4 hv = *(const float4*)&sh[tok][ssrc[e]][d4];
            acc.x += al*hv.x; acc.y += al*hv.y; acc.z += al*hv.z; acc.w += al*hv.w;
        }
        float4 gb = *(const float4*)&gat_b[d4];
        acc.x += gb.x; acc.y += gb.y; acc.z += gb.z; acc.w += gb.w;
        *(float4*)&sagg[tok][n][d4] = acc;
    }
    __syncthreads();

    // warp-parallel LN per node (4 warps per token)
    int lane = ltid & 31, w = ltid >> 5;
    for (int n = w; n < NN; n += 4) {
        float v0 = sagg[tok][n][lane];
        float v1 = sagg[tok][n][lane + 32];
        float v2 = sagg[tok][n][lane + 64];
        float v3 = sagg[tok][n][lane + 96];
        float s1 = v0 + v1 + v2 + v3;
        float s2 = v0*v0 + v1*v1 + v2*v2 + v3*v3;
        #pragma unroll
        for (int o = 16; o > 0; o >>= 1) {
            s1 += __shfl_xor_sync(0xffffffffu, s1, o);
            s2 += __shfl_xor_sync(0xffffffffu, s2, o);
        }
        float mu = s1 * (1.f / DD);
        float var = s2 * (1.f / DD) - mu * mu;
        float rstd = rsqrtf(var + 1e-5f);
        sln[tok][n][lane]      = (v0 - mu) * rstd * gln_g[lane]      + gln_b[lane];
        sln[tok][n][lane + 32] = (v1 - mu) * rstd * gln_g[lane + 32] + gln_b[lane + 32];
        sln[tok][n][lane + 64] = (v2 - mu) * rstd * gln_g[lane + 64] + gln_b[lane + 64];
        sln[tok][n][lane + 96] = (v3 - mu) * rstd * gln_g[lane + 96] + gln_b[lane + 96];
    }
    __syncthreads();

    int d = ltid;
    float zacc = (sln[tok][0][d] + sln[tok][1][d] + sln[tok][2][d] +
                  sln[tok][3][d] + sln[tok][4][d]) * (1.f / NN);

    int t = bt % TT;
    float arg = (float)t * __expf(-(float)((d >> 1) << 1) * (logf(10000.f) / (float)DD));
    zacc += (d & 1) ? cosf(arg) : sinf(arg);
    z[(size_t)bt * DD + d]   = zacc;
    ztf[(size_t)bt * DD + d] = to_tf32(zacc);
}

// ---------------- tf32 tensor-core GEMM, fully async 4-stage pipeline -------
#define TFS 136
#define AS_WORDS (128*20)
#define BS_WORDS (16*TFS)
#define STAGE_WORDS (AS_WORDS + BS_WORDS)
template<int EPI>
__global__ void __launch_bounds__(256)
gemm_tf32(const uint32_t* __restrict__ A, const uint32_t* __restrict__ Bm,
          const float* __restrict__ bias, float* __restrict__ Cm,
          uint32_t* __restrict__ Ctf,
          const float* __restrict__ resid,
          const float* __restrict__ ln_g, const float* __restrict__ ln_b,
          int M, int N, int K)
{
    extern __shared__ char smem_raw[];
    uint32_t* Ss = (uint32_t*)smem_raw;

    int tid = threadIdx.x;
    int warp = tid >> 5, lane = tid & 31;
    int tig = lane & 3, grp = lane >> 2;
    int wm = warp >> 2, wn = warp & 3;
    int m0 = blockIdx.y * 128, n0 = blockIdx.x * 128;
    int nk = K >> 4;

    float acc[4][4][4];
    #pragma unroll
    for (int i = 0; i < 4; i++)
        #pragma unroll
        for (int j = 0; j < 4; j++)
            #pragma unroll
            for (int c = 0; c < 4; c++) acc[i][j][c] = 0.f;

    auto issue_stage = [&](int kt) {
        uint32_t* Asb = Ss + (kt & 3) * STAGE_WORDS;
        uint32_t* Bsb = Asb + AS_WORDS;
        int k0 = kt * 16;
        #pragma unroll
        for (int l = 0; l < 2; l++) {
            int f = tid + l*256;
            int ma = f >> 2, kc = (f & 3) * 4;
            cp_async16(&Asb[ma*20 + kc], &A[(size_t)(m0 + ma)*K + k0 + kc]);
        }
        #pragma unroll
        for (int l = 0; l < 2; l++) {
            int f = tid + l*256;
            int kb = f >> 5, nc = (f & 31) * 4;
            cp_async16(&Bsb[kb*TFS + nc], &Bm[(size_t)(k0 + kb)*N + n0 + nc]);
        }
        asm volatile("cp.async.commit_group;");
    };

    issue_stage(0);
    issue_stage(1);
    issue_stage(2);

    for (int kt = 0; kt < nk; kt++) {
        asm volatile("cp.async.wait_group 2;");
        __syncthreads();
        if (kt + 3 < nk) issue_stage(kt + 3);
        else asm volatile("cp.async.commit_group;");

        uint32_t* Asb = Ss + (kt & 3) * STAGE_WORDS;
        uint32_t* Bsb = Asb + AS_WORDS;

        #pragma unroll
        for (int ks = 0; ks < 2; ks++) {
            int kb = ks*8;
            uint32_t afr[4][4];
            #pragma unroll
            for (int mf = 0; mf < 4; mf++) {
                int r0 = wm*64 + mf*16 + grp;
                afr[mf][0] = Asb[r0*20       + kb + tig];
                afr[mf][1] = Asb[(r0 + 8)*20 + kb + tig];
                afr[mf][2] = Asb[r0*20       + kb + tig + 4];
                afr[mf][3] = Asb[(r0 + 8)*20 + kb + tig + 4];
            }
            uint32_t bfr[4][2];
            #pragma unroll
            for (int nf = 0; nf < 4; nf++) {
                int c0 = wn*32 + nf*8 + grp;
                bfr[nf][0] = Bsb[(kb + tig)*TFS + c0];
                bfr[nf][1] = Bsb[(kb + tig + 4)*TFS + c0];
            }
            #pragma unroll
            for (int mf = 0; mf < 4; mf++)
                #pragma unroll
                for (int nf = 0; nf < 4; nf++)
                    mma_tf32(acc[mf][nf], afr[mf], bfr[nf]);
        }
    }
    __syncthreads();

    if (EPI == 2) {
        float* Cs = (float*)smem_raw;
        #pragma unroll
        for (int mf = 0; mf < 4; mf++) {
            int r = wm*64 + mf*16 + grp;
            #pragma unroll
            for (int nf = 0; nf < 4; nf++) {
                int c = wn*32 + nf*8 + 2*tig;
                Cs[r*132 + c]           = acc[mf][nf][0];
                Cs[r*132 + c + 1]       = acc[mf][nf][1];
                Cs[(r + 8)*132 + c]     = acc[mf][nf][2];
                Cs[(r + 8)*132 + c + 1] = acc[mf][nf][3];
            }
        }
        __syncthreads();

        float4 bb = *(const float4*)&bias[lane*4];
        float4 gg = *(const float4*)&ln_g[lane*4];
        float4 be = *(const float4*)&ln_b[lane*4];
        for (int r = warp*16; r < warp*16 + 16; r++) {
            int m = m0 + r;
            float4 cv = *(const float4*)&Cs[r*132 + lane*4];
            float4 zv = *(const float4*)&resid[(size_t)m*128 + lane*4];
            float v[4] = {cv.x + bb.x + zv.x, cv.y + bb.y + zv.y,
                          cv.z + bb.z + zv.z, cv.w + bb.w + zv.w};
            float s = v[0] + v[1] + v[2] + v[3];
            #pragma unroll
            for (int o = 16; o > 0; o >>= 1) s += __shfl_xor_sync(0xffffffffu, s, o);
            float mu = s * (1.f / 128.f);
            float q = 0.f;
            #pragma unroll
            for (int j = 0; j < 4; j++) { float dv = v[j] - mu; q += dv * dv; }
            #pragma unroll
            for (int o = 16; o > 0; o >>= 1) q += __shfl_xor_sync(0xffffffffu, q, o);
            float rstd = rsqrtf(q * (1.f / 128.f) + 1e-5f);
            float4 rv;
            rv.x = (v[0] - mu) * rstd * gg.x + be.x;
            rv.y = (v[1] - mu) * rstd * gg.y + be.y;
            rv.z = (v[2] - mu) * rstd * gg.z + be.z;
            rv.w = (v[3] - mu) * rstd * gg.w + be.w;
            *(float4*)&Cm[(size_t)m*128 + lane*4] = rv;
            uint4 tv;
            tv.x = to_tf32(rv.x); tv.y = to_tf32(rv.y);
            tv.z = to_tf32(rv.z); tv.w = to_tf32(rv.w);
            *(uint4*)&Ctf[(size_t)m*128 + lane*4] = tv;
        }
    } else {
        #pragma unroll
        for (int mf = 0; mf < 4; mf++) {
            int r = m0 + wm*64 + mf*16 + grp;
            #pragma unroll
            for (int nf = 0; nf < 4; nf++) {
                int c = n0 + wn*32 + nf*8 + 2*tig;
                float b0 = bias[c], b1 = bias[c + 1];
                float v0 = acc[mf][nf][0] + b0;
                float v1 = acc[mf][nf][1] + b1;
                float v2 = acc[mf][nf][2] + b0;
                float v3 = acc[mf][nf][3] + b1;
                if (EPI == 1) {
                    v0 = fmaxf(v0, 0.f); v1 = fmaxf(v1, 0.f);
                    v2 = fmaxf(v2, 0.f); v3 = fmaxf(v3, 0.f);
                    *(uint2*)&Ctf[(size_t)r*N + c]       = make_uint2(to_tf32(v0), to_tf32(v1));
                    *(uint2*)&Ctf[(size_t)(r + 8)*N + c] = make_uint2(to_tf32(v2), to_tf32(v3));
                } else {
                    *(float2*)&Cm[(size_t)r*N + c]       = make_float2(v0, v1);
                    *(float2*)&Cm[(size_t)(r + 8)*N + c] = make_float2(v2, v3);
                }
            }
        }
    }
}

// ---------------- attention per (b, head): R15 version (balanced 4x6) -------
#define QKS 36
#define SSS 76
__global__ void __launch_bounds__(256, 4)
attn_kernel(const float* __restrict__ qkv, uint32_t* __restrict__ obuf)
{
    int b = blockIdx.x;
    int h = blockIdx.y;
    int tid = threadIdx.x;  // 256

    __shared__ __align__(16) float sq[TT*QKS];
    __shared__ __align__(16) float skv[TT*QKS];
    __shared__ __align__(16) float sS[TT*SSS];

    const float* base = qkv + (size_t)b * TT * (3*DD) + h*DHEAD;
    for (int idx = tid; idx < TT*DHEAD; idx += 256) {
        int t = idx >> 5, d = idx & 31;
        sq[t*QKS + d]  = base[t*(3*DD)      + d];
        skv[t*QKS + d] = base[t*(3*DD) + DD + d];
    }
    __syncthreads();

    const float inv_scale = rsqrtf((float)DHEAD);
    for (int tt = tid; tt < 216; tt += 256) {
        int i0 = (tt / 12) * 4, j0 = (tt % 12) * 6;
        float acc[4][6];
        #pragma unroll
        for (int a = 0; a < 4; a++)
            #pragma unroll
            for (int c = 0; c < 6; c++) acc[a][c] = 0.f;
        #pragma unroll
        for (int d4 = 0; d4 < DHEAD; d4 += 4) {
            float4 q[4], k[6];
            #pragma unroll
            for (int a = 0; a < 4; a++) q[a] = *(const float4*)&sq[(i0+a)*QKS + d4];
            #pragma unroll
            for (int c = 0; c < 6; c++) k[c] = *(const float4*)&skv[(j0+c)*QKS + d4];
            #pragma unroll
            for (int a = 0; a < 4; a++)
                #pragma unroll
                for (int c = 0; c < 6; c++)
                    acc[a][c] += q[a].x*k[c].x + q[a].y*k[c].y + q[a].z*k[c].z + q[a].w*k[c].w;
        }
        #pragma unroll
        for (int a = 0; a < 4; a++)
            #pragma unroll
            for (int c = 0; c < 6; c++)
                sS[(i0+a)*SSS + j0 + c] = acc[a][c] * inv_scale;
    }
    __syncthreads();

    int wid = tid >> 5, lane = tid & 31;
    for (int i = wid; i < TT; i += 8) {
        float m = -1e30f;
        for (int j = lane; j < TT; j += 32) m = fmaxf(m, sS[i*SSS + j]);
        #pragma unroll
        for (int o = 16; o > 0; o >>= 1) m = fmaxf(m, __shfl_xor_sync(0xffffffffu, m, o));
        float s = 0.f;
        for (int j = lane; j < TT; j += 32) {
            float e = __expf(sS[i*SSS + j] - m);
            sS[i*SSS + j] = e;
            s += e;
        }
        #pragma unroll
        for (int o = 16; o > 0; o >>= 1) s += __shfl_xor_sync(0xffffffffu, s, o);
        float inv = 1.f / s;
        for (int j = lane; j < TT; j += 32) sS[i*SSS + j] *= inv;
    }
    __syncthreads();

    for (int idx = tid; idx < TT*DHEAD; idx += 256) {
        int t = idx >> 5, d = idx & 31;
        skv[t*QKS + d] = base[t*(3*DD) + 2*DD + d];
    }
    __syncthreads();

    for (int tt = tid; tt < 144; tt += 256) {
        int i0 = (tt >> 2) * 2;
        int d0 = (tt & 3) * 8;
        float acc0[8], acc1[8];
        #pragma unroll
        for (int c = 0; c < 8; c++) { acc0[c] = 0.f; acc1[c] = 0.f; }
        for (int j = 0; j < TT; j++) {
            float s0 = sS[i0*SSS + j];
            float s1 = sS[(i0+1)*SSS + j];
            float4 v0 = *(const float4*)&skv[j*QKS + d0];
            float4 v1 = *(const float4*)&skv[j*QKS + d0 + 4];
            acc0[0] += s0*v0.x; acc0[1] += s0*v0.y; acc0[2] += s0*v0.z; acc0[3] += s0*v0.w;
            acc0[4] += s0*v1.x; acc0[5] += s0*v1.y; acc0[6] += s0*v1.z; acc0[7] += s0*v1.w;
            acc1[0] += s1*v0.x; acc1[1] += s1*v0.y; acc1[2] += s1*v0.z; acc1[3] += s1*v0.w;
            acc1[4] += s1*v1.x; acc1[5] += s1*v1.y; acc1[6] += s1*v1.z; acc1[7] += s1*v1.w;
        }
        uint32_t* o0 = &obuf[((size_t)b*TT + i0)*DD + h*DHEAD + d0];
        uint32_t* o1 = o0 + DD;
        *(uint4*)o0       = make_uint4(to_tf32(acc0[0]), to_tf32(acc0[1]), to_tf32(acc0[2]), to_tf32(acc0[3]));
        *(uint4*)(o0 + 4) = make_uint4(to_tf32(acc0[4]), to_tf32(acc0[5]), to_tf32(acc0[6]), to_tf32(acc0[7]));
        *(uint4*)o1       = make_uint4(to_tf32(acc1[0]), to_tf32(acc1[1]), to_tf32(acc1[2]), to_tf32(acc1[3]));
        *(uint4*)(o1 + 4) = make_uint4(to_tf32(acc1[4]), to_tf32(acc1[5]), to_tf32(acc1[6]), to_tf32(acc1[7]));
    }
}

// ---------------- 6 MLP heads on last timestep ----------------
__global__ void heads_kernel(const float* __restrict__ z,
                             const float* __restrict__ hw1, const float* __restrict__ hb1,
                             const float* __restrict__ hw2, const float* __restrict__ hb2,
                             float* __restrict__ out)
{
    int b = blockIdx.x;
    int k = blockIdx.y;
    int tid = threadIdx.x;  // 64
    __shared__ float slast[DD];
    __shared__ float sh1[64];
    const float* zr = z + ((size_t)b*TT + (TT-1))*DD;
    slast[tid] = zr[tid];
    slast[tid + 64] = zr[tid + 64];
    __syncthreads();

    float acc = hb1[k*64 + tid];
    const float* w1 = hw1 + (size_t)k*DD*64;
    #pragma unroll 8
    for (int d = 0; d < DD; d++) acc += slast[d] * w1[d*64 + tid];
    sh1[tid] = fmaxf(acc, 0.f);
    __syncthreads();

    if (tid < 5) {
        float a2 = hb2[k*5 + tid];
        const float* w2 = hw2 + (size_t)k*64*5;
        #pragma unroll 8
        for (int m = 0; m < 64; m++) a2 += sh1[m] * w2[m*5 + tid];
        out[((size_t)k*BB + b)*5 + tid] = a2;
    }
}

// ---------------- launcher ----------------
extern "C" void kernel_launch(void* const* d_in, const int* in_sizes, int n_in,
                              void* d_out, int out_size)
{
    const float* x        = (const float*)d_in[0];
    const int*   ei       = (const int*)  d_in[1];
    const float* gcn_w    = (const float*)d_in[2];
    const float* gcn_b    = (const float*)d_in[3];
    const float* gat_w    = (const float*)d_in[4];
    const float* gat_a_s  = (const float*)d_in[5];
    const float* gat_a_d  = (const float*)d_in[6];
    const float* gat_b    = (const float*)d_in[7];
    const float* gln_g    = (const float*)d_in[8];
    const float* gln_b    = (const float*)d_in[9];
    const float* tw_qkv   = (const float*)d_in[10];
    const float* tb_qkv   = (const float*)d_in[11];
    const float* tw_o     = (const float*)d_in[12];
    const float* tb_o     = (const float*)d_in[13];
    const float* ln1_g    = (const float*)d_in[14];
    const float* ln1_b    = (const float*)d_in[15];
    const float* w_ff1    = (const float*)d_in[16];
    const float* b_ff1    = (const float*)d_in[17];
    const float* w_ff2    = (const float*)d_in[18];
    const float* b_ff2    = (const float*)d_in[19];
    const float* ln2_g    = (const float*)d_in[20];
    const float* ln2_b    = (const float*)d_in[21];
    const float* hw1      = (const float*)d_in[22];
    const float* hb1      = (const float*)d_in[23];
    const float* hw2      = (const float*)d_in[24];
    const float* hb2      = (const float*)d_in[25];
    float* out = (float*)d_out;

    float *zp, *qkvp;
    uint32_t *wtf, *ztf, *otf, *fftf;
    cudaGetSymbolAddress((void**)&zp,   d_z);
    cudaGetSymbolAddress((void**)&qkvp, d_qkv);
    cudaGetSymbolAddress((void**)&wtf,  d_wtf);
    cudaGetSymbolAddress((void**)&ztf,  d_ztf);
    cudaGetSymbolAddress((void**)&otf,  d_otf);
    cudaGetSymbolAddress((void**)&fftf, d_fftf);

    const int SMEM_PIPE = 4 * STAGE_WORDS * 4;    // 75776 B
    static bool attr_set = false;
    if (!attr_set) {
        cudaFuncSetAttribute(gemm_tf32<0>, cudaFuncAttributeMaxDynamicSharedMemorySize, SMEM_PIPE);
        cudaFuncSetAttribute(gemm_tf32<1>, cudaFuncAttributeMaxDynamicSharedMemorySize, SMEM_PIPE);
        cudaFuncSetAttribute(gemm_tf32<2>, cudaFuncAttributeMaxDynamicSharedMemorySize, SMEM_PIPE);
        attr_set = true;
    }

    int E = in_sizes[1] / 2;

    build_graph_kernel<<<1, 32>>>(ei, E);
    cvt_weights_kernel<<<192, 256>>>(tw_qkv, tw_o, w_ff1, w_ff2);

    gcn_gat_kernel<<<BT/2, 256>>>(x, gcn_w, gcn_b, gat_w, gat_a_s, gat_a_d,
                                  gat_b, gln_g, gln_b, zp, ztf, E + NN);

    for (int i = 0; i < 3; i++) {
        gemm_tf32<0><<<dim3((3*DD)/128, BT/128), 256, SMEM_PIPE>>>(
            ztf, wtf + WOFF_QKV + (size_t)i*DD*3*DD, tb_qkv + (size_t)i*3*DD, qkvp,
            nullptr, nullptr, nullptr, nullptr, BT, 3*DD, DD);
        attn_kernel<<<dim3(BB, NHEAD), 256>>>(qkvp, otf);
        gemm_tf32<2><<<dim3(1, BT/128), 256, SMEM_PIPE>>>(
            otf, wtf + WOFF_O + (size_t)i*DD*DD, tb_o + (size_t)i*DD, zp,
            ztf, zp, ln1_g + (size_t)i*DD, ln1_b + (size_t)i*DD, BT, DD, DD);
        gemm_tf32<1><<<dim3(FFD/128, BT/128), 256, SMEM_PIPE>>>(
            ztf, wtf + WOFF_FF1 + (size_t)i*DD*FFD, b_ff1 + (size_t)i*FFD, nullptr,
            fftf, nullptr, nullptr, nullptr, BT, FFD, DD);
        gemm_tf32<2><<<dim3(1, BT/128), 256, SMEM_PIPE>>>(
            fftf, wtf + WOFF_FF2 + (size_t)i*FFD*DD, b_ff2 + (size_t)i*DD, zp,
            ztf, zp, ln2_g + (size_t)i*DD, ln2_b + (size_t)i*DD, BT, DD, FFD);
    }

    heads_kernel<<<dim3(BB, 6), 64>>>(zp, hw1, hb1, hw2, hb2, out);
}

// round 17
// speedup vs baseline: 1.0510x; 1.0510x over previous
#include <cuda_runtime.h>
#include <math.h>
#include <stdint.h>

// Problem constants (fixed by reference)
#define BB 256
#define TT 72
#define NN 5
#define FF_IN 10
#define HH 4
#define CC 32
#define DD 128
#define FFD 256
#define NHEAD 4
#define DHEAD 32
#define BT (BB*TT)   // 18432

// ---------------- device scratch (no allocations allowed) ----------------
__device__ float    d_z[BT*DD];
__device__ float    d_qkv[BT*3*DD];
__device__ uint32_t d_ztf[BT*DD];
__device__ uint32_t d_otf[BT*DD];
__device__ uint32_t d_fftf[BT*FFD];
__device__ float    d_Anorm[NN*NN];
__device__ int      d_src2[64];
__device__ int      d_dst2[64];
__device__ int      d_rowptr[NN+1];

// pre-converted tf32 weights: [qkv | o | ff1 | ff2]
#define WOFF_QKV 0
#define WOFF_O   (3*DD*3*DD)
#define WOFF_FF1 (WOFF_O + 3*DD*DD)
#define WOFF_FF2 (WOFF_FF1 + 3*DD*FFD)
#define WTF_TOTAL (WOFF_FF2 + 3*FFD*DD)
__device__ uint32_t d_wtf[WTF_TOTAL];

// ---------------- tf32 helpers ----------------
__device__ __forceinline__ uint32_t to_tf32(float x) {
    uint32_t r;
    asm("cvt.rna.tf32.f32 %0, %1;" : "=r"(r) : "f"(x));
    return r;
}
__device__ __forceinline__ void mma_tf32(float* d, const uint32_t* a, const uint32_t* b) {
    asm volatile(
        "mma.sync.aligned.m16n8k8.row.col.f32.tf32.tf32.f32 "
        "{%0,%1,%2,%3}, {%4,%5,%6,%7}, {%8,%9}, {%0,%1,%2,%3};"
        : "+f"(d[0]), "+f"(d[1]), "+f"(d[2]), "+f"(d[3])
        : "r"(a[0]), "r"(a[1]), "r"(a[2]), "r"(a[3]), "r"(b[0]), "r"(b[1]));
}
__device__ __forceinline__ void cp_async16(void* smem_dst, const void* gmem_src) {
    uint32_t s = (uint32_t)__cvta_generic_to_shared(smem_dst);
    asm volatile("cp.async.ca.shared.global [%0], [%1], 16;" :: "r"(s), "l"(gmem_src));
}
__device__ __forceinline__ float fast_tanh(float x) {
    x = fminf(fmaxf(x, -15.f), 15.f);
    float e = __expf(2.f * x);
    return (e - 1.f) / (e + 1.f);
}

// ---------------- weight pre-conversion (rna, once per launch) ----------------
__global__ void cvt_weights_kernel(const float* __restrict__ qkv, const float* __restrict__ o,
                                   const float* __restrict__ ff1, const float* __restrict__ ff2)
{
    int i = blockIdx.x * blockDim.x + threadIdx.x;
    int stride = gridDim.x * blockDim.x;
    for (int idx = i; idx < 3*DD*3*DD; idx += stride) d_wtf[WOFF_QKV + idx] = to_tf32(qkv[idx]);
    for (int idx = i; idx < 3*DD*DD;   idx += stride) d_wtf[WOFF_O   + idx] = to_tf32(o[idx]);
    for (int idx = i; idx < 3*DD*FFD;  idx += stride) d_wtf[WOFF_FF1 + idx] = to_tf32(ff1[idx]);
    for (int idx = i; idx < 3*FFD*DD;  idx += stride) d_wtf[WOFF_FF2 + idx] = to_tf32(ff2[idx]);
}

// ---------------- graph build: Anorm + dst-sorted CSR ----------------
__global__ void build_graph_kernel(const int* __restrict__ ei, int E) {
    if (threadIdx.x != 0 || blockIdx.x != 0) return;
    float A[NN][NN];
    for (int i = 0; i < NN*NN; i++) ((float*)A)[i] = 0.f;
    int ts[64], td[64];
    int E2 = E + NN;
    for (int e = 0; e < E; e++) {
        int s = ei[e], d = ei[E + e];
        A[d][s] += 1.f;
        ts[e] = s; td[e] = d;
    }
    for (int n = 0; n < NN; n++) {
        A[n][n] += 1.f;
        ts[E + n] = n; td[E + n] = n;
    }
    int cnt[NN];
    for (int n = 0; n < NN; n++) cnt[n] = 0;
    for (int e = 0; e < E2; e++) cnt[td[e]]++;
    d_rowptr[0] = 0;
    for (int n = 0; n < NN; n++) d_rowptr[n+1] = d_rowptr[n] + cnt[n];
    int pos[NN];
    for (int n = 0; n < NN; n++) pos[n] = d_rowptr[n];
    for (int e = 0; e < E2; e++) {
        int p = pos[td[e]]++;
        d_src2[p] = ts[e];
        d_dst2[p] = td[e];
    }
    float dinv[NN];
    for (int n = 0; n < NN; n++) {
        float s = 0.f;
        for (int j = 0; j < NN; j++) s += A[n][j];
        dinv[n] = (s > 0.f) ? (1.f / sqrtf(s)) : 0.f;
    }
    for (int i = 0; i < NN; i++)
        for (int j = 0; j < NN; j++)
            d_Anorm[i*NN + j] = dinv[i] * A[i][j] * dinv[j];
}

// ---------------- fused GCN + GAT + LN + node-mean + PE (R15 version) -------
__global__ void gcn_gat_kernel(
    const float* __restrict__ x,
    const float* __restrict__ gcn_w, const float* __restrict__ gcn_b,
    const float* __restrict__ gat_w, const float* __restrict__ a_src,
    const float* __restrict__ a_dst, const float* __restrict__ gat_b,
    const float* __restrict__ gln_g, const float* __restrict__ gln_b,
    float* __restrict__ z, uint32_t* __restrict__ ztf, int E2)
{
    int bt = blockIdx.x;
    int tid = threadIdx.x;  // 128

    __shared__ __align__(16) float sxw[NN][64];
    __shared__ __align__(16) float sgcn[NN][64];
    __shared__ __align__(16) float sh[NN][DD];
    __shared__ __align__(16) float sagg[NN][DD];
    __shared__ __align__(16) float sln[NN][DD];
    __shared__ float sx[NN][FF_IN];
    __shared__ float sas[NN][HH], sad[NN][HH];
    __shared__ float se[32][HH];
    __shared__ float salpha[32][HH];
    __shared__ float smx[NN][HH], sden[NN][HH];
    __shared__ float sAn[NN*NN];
    __shared__ int   ssrc[32], sdst[32];
    __shared__ int   srp[NN+1];

    const float* xp = x + (size_t)bt * NN * FF_IN;
    if (tid < NN*FF_IN) ((float*)sx)[tid] = xp[tid];
    if (tid < NN*NN) sAn[tid] = d_Anorm[tid];
    if (tid < E2) { ssrc[tid] = d_src2[tid]; sdst[tid] = d_dst2[tid]; }
    if (tid < NN+1) srp[tid] = d_rowptr[tid];
    __syncthreads();

    for (int idx = tid; idx < NN*16; idx += 128) {
        int n = idx >> 4, c4 = (idx & 15) * 4;
        float4 acc = *(const float4*)&gcn_b[c4];
        #pragma unroll
        for (int f = 0; f < FF_IN; f++) {
            float xv = sx[n][f];
            float4 w = *(const float4*)&gcn_w[f*64 + c4];
            acc.x += xv*w.x; acc.y += xv*w.y; acc.z += xv*w.z; acc.w += xv*w.w;
        }
        *(float4*)&sxw[n][c4] = acc;
    }
    __syncthreads();

    for (int idx = tid; idx < NN*16; idx += 128) {
        int n = idx >> 4, c4 = (idx & 15) * 4;
        float4 acc = make_float4(0.f, 0.f, 0.f, 0.f);
        #pragma unroll
        for (int m = 0; m < NN; m++) {
            float a = sAn[n*NN + m];
            float4 xw = *(const float4*)&sxw[m][c4];
            acc.x += a*xw.x; acc.y += a*xw.y; acc.z += a*xw.z; acc.w += a*xw.w;
        }
        acc.x = fast_tanh(acc.x); acc.y = fast_tanh(acc.y);
        acc.z = fast_tanh(acc.z); acc.w = fast_tanh(acc.w);
        *(float4*)&sgcn[n][c4] = acc;
    }
    __syncthreads();

    for (int idx = tid; idx < NN*32; idx += 128) {
        int n = idx >> 5, d4 = (idx & 31) * 4;
        float4 acc = make_float4(0.f, 0.f, 0.f, 0.f);
        #pragma unroll 8
        for (int f = 0; f < 64; f++) {
            float g = sgcn[n][f];
            float4 w = *(const float4*)&gat_w[f*DD + d4];
            acc.x += g*w.x; acc.y += g*w.y; acc.z += g*w.z; acc.w += g*w.w;
        }
        *(float4*)&sh[n][d4] = acc;
    }
    __syncthreads();

    if (tid < NN*HH*2) {
        int n = tid / (HH*2), r = tid % (HH*2), hd = r >> 1, which = r & 1;
        const float* av = which ? a_dst : a_src;
        float acc = 0.f;
        #pragma unroll
        for (int c = 0; c < CC; c++) acc += sh[n][hd*CC + c] * av[hd*CC + c];
        if (which) sad[n][hd] = acc; else sas[n][hd] = acc;
    }
    __syncthreads();

    for (int idx = tid; idx < E2*HH; idx += 128) {
        int e = idx >> 2, hd = idx & 3;
        float v = sas[ssrc[e]][hd] + sad[sdst[e]][hd];
        se[e][hd] = (v > 0.f) ? v : 0.2f * v;
    }
    __syncthreads();

    if (tid < NN*HH) {
        int n = tid >> 2, hd = tid & 3;
        int e0 = srp[n], e1 = srp[n+1];
        float m = -1e30f;
        for (int e = e0; e < e1; e++) m = fmaxf(m, se[e][hd]);
        float s = 0.f;
        for (int e = e0; e < e1; e++) s += __expf(se[e][hd] - m);
        smx[n][hd] = m; sden[n][hd] = s;
    }
    __syncthreads();

    for (int idx = tid; idx < E2*HH; idx += 128) {
        int e = idx >> 2, hd = idx & 3;
        int n = sdst[e];
        salpha[e][hd] = __expf(se[e][hd] - smx[n][hd]) / sden[n][hd];
    }
    __syncthreads();

    for (int idx = tid; idx < NN*32; idx += 128) {
        int n = idx >> 5, d4 = (idx & 31) * 4;
        int hd = d4 >> 5;
        int e0 = srp[n], e1 = srp[n+1];
        float4 acc = make_float4(0.f, 0.f, 0.f, 0.f);
        for (int e = e0; e < e1; e++) {
            float al = salpha[e][hd];
            float4 hv = *(const float4*)&sh[ssrc[e]][d4];
            acc.x += al*hv.x; acc.y += al*hv.y; acc.z += al*hv.z; acc.w += al*hv.w;
        }
        float4 gb = *(const float4*)&gat_b[d4];
        acc.x += gb.x; acc.y += gb.y; acc.z += gb.z; acc.w += gb.w;
        *(float4*)&sagg[n][d4] = acc;
    }
    __syncthreads();

    int lane = tid & 31, wid = tid >> 5;
    for (int n = wid; n < NN; n += 4) {
        float v0 = sagg[n][lane];
        float v1 = sagg[n][lane + 32];
        float v2 = sagg[n][lane + 64];
        float v3 = sagg[n][lane + 96];
        float s1 = v0 + v1 + v2 + v3;
        float s2 = v0*v0 + v1*v1 + v2*v2 + v3*v3;
        #pragma unroll
        for (int o = 16; o > 0; o >>= 1) {
            s1 += __shfl_xor_sync(0xffffffffu, s1, o);
            s2 += __shfl_xor_sync(0xffffffffu, s2, o);
        }
        float mu = s1 * (1.f / DD);
        float var = s2 * (1.f / DD) - mu * mu;
        float rstd = rsqrtf(var + 1e-5f);
        sln[n][lane]      = (v0 - mu) * rstd * gln_g[lane]      + gln_b[lane];
        sln[n][lane + 32] = (v1 - mu) * rstd * gln_g[lane + 32] + gln_b[lane + 32];
        sln[n][lane + 64] = (v2 - mu) * rstd * gln_g[lane + 64] + gln_b[lane + 64];
        sln[n][lane + 96] = (v3 - mu) * rstd * gln_g[lane + 96] + gln_b[lane + 96];
    }
    __syncthreads();

    int d = tid;
    float zacc = (sln[0][d] + sln[1][d] + sln[2][d] + sln[3][d] + sln[4][d]) * (1.f / NN);

    int t = bt % TT;
    float arg = (float)t * __expf(-(float)((d >> 1) << 1) * (logf(10000.f) / (float)DD));
    zacc += (d & 1) ? cosf(arg) : sinf(arg);
    z[(size_t)bt * DD + d]   = zacc;
    ztf[(size_t)bt * DD + d] = to_tf32(zacc);
}

// ---------------- tf32 tensor-core GEMM, fully async 4-stage pipeline -------
#define TFS 136
#define AS_WORDS (128*20)
#define BS_WORDS (16*TFS)
#define STAGE_WORDS (AS_WORDS + BS_WORDS)
template<int EPI>
__global__ void __launch_bounds__(256)
gemm_tf32(const uint32_t* __restrict__ A, const uint32_t* __restrict__ Bm,
          const float* __restrict__ bias, float* __restrict__ Cm,
          uint32_t* __restrict__ Ctf,
          const float* __restrict__ resid,
          const float* __restrict__ ln_g, const float* __restrict__ ln_b,
          int M, int N, int K)
{
    extern __shared__ char smem_raw[];
    uint32_t* Ss = (uint32_t*)smem_raw;

    int tid = threadIdx.x;
    int warp = tid >> 5, lane = tid & 31;
    int tig = lane & 3, grp = lane >> 2;
    int wm = warp >> 2, wn = warp & 3;
    int m0 = blockIdx.y * 128, n0 = blockIdx.x * 128;
    int nk = K >> 4;

    float acc[4][4][4];
    #pragma unroll
    for (int i = 0; i < 4; i++)
        #pragma unroll
        for (int j = 0; j < 4; j++)
            #pragma unroll
            for (int c = 0; c < 4; c++) acc[i][j][c] = 0.f;

    auto issue_stage = [&](int kt) {
        uint32_t* Asb = Ss + (kt & 3) * STAGE_WORDS;
        uint32_t* Bsb = Asb + AS_WORDS;
        int k0 = kt * 16;
        #pragma unroll
        for (int l = 0; l < 2; l++) {
            int f = tid + l*256;
            int ma = f >> 2, kc = (f & 3) * 4;
            cp_async16(&Asb[ma*20 + kc], &A[(size_t)(m0 + ma)*K + k0 + kc]);
        }
        #pragma unroll
        for (int l = 0; l < 2; l++) {
            int f = tid + l*256;
            int kb = f >> 5, nc = (f & 31) * 4;
            cp_async16(&Bsb[kb*TFS + nc], &Bm[(size_t)(k0 + kb)*N + n0 + nc]);
        }
        asm volatile("cp.async.commit_group;");
    };

    issue_stage(0);
    issue_stage(1);
    issue_stage(2);

    for (int kt = 0; kt < nk; kt++) {
        asm volatile("cp.async.wait_group 2;");
        __syncthreads();
        if (kt + 3 < nk) issue_stage(kt + 3);
        else asm volatile("cp.async.commit_group;");

        uint32_t* Asb = Ss + (kt & 3) * STAGE_WORDS;
        uint32_t* Bsb = Asb + AS_WORDS;

        #pragma unroll
        for (int ks = 0; ks < 2; ks++) {
            int kb = ks*8;
            uint32_t afr[4][4];
            #pragma unroll
            for (int mf = 0; mf < 4; mf++) {
                int r0 = wm*64 + mf*16 + grp;
                afr[mf][0] = Asb[r0*20       + kb + tig];
                afr[mf][1] = Asb[(r0 + 8)*20 + kb + tig];
                afr[mf][2] = Asb[r0*20       + kb + tig + 4];
                afr[mf][3] = Asb[(r0 + 8)*20 + kb + tig + 4];
            }
            uint32_t bfr[4][2];
            #pragma unroll
            for (int nf = 0; nf < 4; nf++) {
                int c0 = wn*32 + nf*8 + grp;
                bfr[nf][0] = Bsb[(kb + tig)*TFS + c0];
                bfr[nf][1] = Bsb[(kb + tig + 4)*TFS + c0];
            }
            #pragma unroll
            for (int mf = 0; mf < 4; mf++)
                #pragma unroll
                for (int nf = 0; nf < 4; nf++)
                    mma_tf32(acc[mf][nf], afr[mf], bfr[nf]);
        }
    }
    __syncthreads();

    if (EPI == 2) {
        float* Cs = (float*)smem_raw;
        #pragma unroll
        for (int mf = 0; mf < 4; mf++) {
            int r = wm*64 + mf*16 + grp;
            #pragma unroll
            for (int nf = 0; nf < 4; nf++) {
                int c = wn*32 + nf*8 + 2*tig;
                Cs[r*132 + c]           = acc[mf][nf][0];
                Cs[r*132 + c + 1]       = acc[mf][nf][1];
                Cs[(r + 8)*132 + c]     = acc[mf][nf][2];
                Cs[(r + 8)*132 + c + 1] = acc[mf][nf][3];
            }
        }
        __syncthreads();

        float4 bb = *(const float4*)&bias[lane*4];
        float4 gg = *(const float4*)&ln_g[lane*4];
        float4 be = *(const float4*)&ln_b[lane*4];
        for (int r = warp*16; r < warp*16 + 16; r++) {
            int m = m0 + r;
            float4 cv = *(const float4*)&Cs[r*132 + lane*4];
            float4 zv = *(const float4*)&resid[(size_t)m*128 + lane*4];
            float v[4] = {cv.x + bb.x + zv.x, cv.y + bb.y + zv.y,
                          cv.z + bb.z + zv.z, cv.w + bb.w + zv.w};
            float s = v[0] + v[1] + v[2] + v[3];
            #pragma unroll
            for (int o = 16; o > 0; o >>= 1) s += __shfl_xor_sync(0xffffffffu, s, o);
            float mu = s * (1.f / 128.f);
            float q = 0.f;
            #pragma unroll
            for (int j = 0; j < 4; j++) { float dv = v[j] - mu; q += dv * dv; }
            #pragma unroll
            for (int o = 16; o > 0; o >>= 1) q += __shfl_xor_sync(0xffffffffu, q, o);
            float rstd = rsqrtf(q * (1.f / 128.f) + 1e-5f);
            float4 rv;
            rv.x = (v[0] - mu) * rstd * gg.x + be.x;
            rv.y = (v[1] - mu) * rstd * gg.y + be.y;
            rv.z = (v[2] - mu) * rstd * gg.z + be.z;
            rv.w = (v[3] - mu) * rstd * gg.w + be.w;
            *(float4*)&Cm[(size_t)m*128 + lane*4] = rv;
            uint4 tv;
            tv.x = to_tf32(rv.x); tv.y = to_tf32(rv.y);
            tv.z = to_tf32(rv.z); tv.w = to_tf32(rv.w);
            *(uint4*)&Ctf[(size_t)m*128 + lane*4] = tv;
        }
    } else {
        #pragma unroll
        for (int mf = 0; mf < 4; mf++) {
            int r = m0 + wm*64 + mf*16 + grp;
            #pragma unroll
            for (int nf = 0; nf < 4; nf++) {
                int c = n0 + wn*32 + nf*8 + 2*tig;
                float b0 = bias[c], b1 = bias[c + 1];
                float v0 = acc[mf][nf][0] + b0;
                float v1 = acc[mf][nf][1] + b1;
                float v2 = acc[mf][nf][2] + b0;
                float v3 = acc[mf][nf][3] + b1;
                if (EPI == 1) {
                    v0 = fmaxf(v0, 0.f); v1 = fmaxf(v1, 0.f);
                    v2 = fmaxf(v2, 0.f); v3 = fmaxf(v3, 0.f);
                    *(uint2*)&Ctf[(size_t)r*N + c]       = make_uint2(to_tf32(v0), to_tf32(v1));
                    *(uint2*)&Ctf[(size_t)(r + 8)*N + c] = make_uint2(to_tf32(v2), to_tf32(v3));
                } else {
                    *(float2*)&Cm[(size_t)r*N + c]       = make_float2(v0, v1);
                    *(float2*)&Cm[(size_t)(r + 8)*N + c] = make_float2(v2, v3);
                }
            }
        }
    }
}

// ---------------- attention per (b, head): R15 + float4 global loads --------
#define QKS 36
#define SSS 76
__global__ void __launch_bounds__(256, 4)
attn_kernel(const float* __restrict__ qkv, uint32_t* __restrict__ obuf)
{
    int b = blockIdx.x;
    int h = blockIdx.y;
    int tid = threadIdx.x;  // 256

    __shared__ __align__(16) float sq[TT*QKS];
    __shared__ __align__(16) float skv[TT*QKS];
    __shared__ __align__(16) float sS[TT*SSS];

    const float* base = qkv + (size_t)b * TT * (3*DD) + h*DHEAD;
    // Q,K loads: float4 (72*8 = 576 items each)
    for (int idx = tid; idx < TT*8; idx += 256) {
        int t = idx >> 3, d4 = (idx & 7) * 4;
        *(float4*)&sq[t*QKS + d4]  = *(const float4*)&base[t*(3*DD)      + d4];
        *(float4*)&skv[t*QKS + d4] = *(const float4*)&base[t*(3*DD) + DD + d4];
    }
    __syncthreads();

    const float inv_scale = rsqrtf((float)DHEAD);
    // S = Q @ K^T : 4x6 register tiles, 18 x 12 = 216 tiles (<=256: no tail)
    for (int tt = tid; tt < 216; tt += 256) {
        int i0 = (tt / 12) * 4, j0 = (tt % 12) * 6;
        float acc[4][6];
        #pragma unroll
        for (int a = 0; a < 4; a++)
            #pragma unroll
            for (int c = 0; c < 6; c++) acc[a][c] = 0.f;
        #pragma unroll
        for (int d4 = 0; d4 < DHEAD; d4 += 4) {
            float4 q[4], k[6];
            #pragma unroll
            for (int a = 0; a < 4; a++) q[a] = *(const float4*)&sq[(i0+a)*QKS + d4];
            #pragma unroll
            for (int c = 0; c < 6; c++) k[c] = *(const float4*)&skv[(j0+c)*QKS + d4];
            #pragma unroll
            for (int a = 0; a < 4; a++)
                #pragma unroll
                for (int c = 0; c < 6; c++)
                    acc[a][c] += q[a].x*k[c].x + q[a].y*k[c].y + q[a].z*k[c].z + q[a].w*k[c].w;
        }
        #pragma unroll
        for (int a = 0; a < 4; a++)
            #pragma unroll
            for (int c = 0; c < 6; c++)
                sS[(i0+a)*SSS + j0 + c] = acc[a][c] * inv_scale;
    }
    __syncthreads();

    int wid = tid >> 5, lane = tid & 31;
    for (int i = wid; i < TT; i += 8) {
        float m = -1e30f;
        for (int j = lane; j < TT; j += 32) m = fmaxf(m, sS[i*SSS + j]);
        #pragma unroll
        for (int o = 16; o > 0; o >>= 1) m = fmaxf(m, __shfl_xor_sync(0xffffffffu, m, o));
        float s = 0.f;
        for (int j = lane; j < TT; j += 32) {
            float e = __expf(sS[i*SSS + j] - m);
            sS[i*SSS + j] = e;
            s += e;
        }
        #pragma unroll
        for (int o = 16; o > 0; o >>= 1) s += __shfl_xor_sync(0xffffffffu, s, o);
        float inv = 1.f / s;
        for (int j = lane; j < TT; j += 32) sS[i*SSS + j] *= inv;
    }
    __syncthreads();

    // V load: float4
    for (int idx = tid; idx < TT*8; idx += 256) {
        int t = idx >> 3, d4 = (idx & 7) * 4;
        *(float4*)&skv[t*QKS + d4] = *(const float4*)&base[t*(3*DD) + 2*DD + d4];
    }
    __syncthreads();

    for (int tt = tid; tt < 144; tt += 256) {
        int i0 = (tt >> 2) * 2;
        int d0 = (tt & 3) * 8;
        float acc0[8], acc1[8];
        #pragma unroll
        for (int c = 0; c < 8; c++) { acc0[c] = 0.f; acc1[c] = 0.f; }
        for (int j = 0; j < TT; j++) {
            float s0 = sS[i0*SSS + j];
            float s1 = sS[(i0+1)*SSS + j];
            float4 v0 = *(const float4*)&skv[j*QKS + d0];
            float4 v1 = *(const float4*)&skv[j*QKS + d0 + 4];
            acc0[0] += s0*v0.x; acc0[1] += s0*v0.y; acc0[2] += s0*v0.z; acc0[3] += s0*v0.w;
            acc0[4] += s0*v1.x; acc0[5] += s0*v1.y; acc0[6] += s0*v1.z; acc0[7] += s0*v1.w;
            acc1[0] += s1*v0.x; acc1[1] += s1*v0.y; acc1[2] += s1*v0.z; acc1[3] += s1*v0.w;
            acc1[4] += s1*v1.x; acc1[5] += s1*v1.y; acc1[6] += s1*v1.z; acc1[7] += s1*v1.w;
        }
        uint32_t* o0 = &obuf[((size_t)b*TT + i0)*DD + h*DHEAD + d0];
        uint32_t* o1 = o0 + DD;
        *(uint4*)o0       = make_uint4(to_tf32(acc0[0]), to_tf32(acc0[1]), to_tf32(acc0[2]), to_tf32(acc0[3]));
        *(uint4*)(o0 + 4) = make_uint4(to_tf32(acc0[4]), to_tf32(acc0[5]), to_tf32(acc0[6]), to_tf32(acc0[7]));
        *(uint4*)o1       = make_uint4(to_tf32(acc1[0]), to_tf32(acc1[1]), to_tf32(acc1[2]), to_tf32(acc1[3]));
        *(uint4*)(o1 + 4) = make_uint4(to_tf32(acc1[4]), to_tf32(acc1[5]), to_tf32(acc1[6]), to_tf32(acc1[7]));
    }
}

// ---------------- 6 MLP heads on last timestep ----------------
__global__ void heads_kernel(const float* __restrict__ z,
                             const float* __restrict__ hw1, const float* __restrict__ hb1,
                             const float* __restrict__ hw2, const float* __restrict__ hb2,
                             float* __restrict__ out)
{
    int b = blockIdx.x;
    int k = blockIdx.y;
    int tid = threadIdx.x;  // 64
    __shared__ float slast[DD];
    __shared__ float sh1[64];
    const float* zr = z + ((size_t)b*TT + (TT-1))*DD;
    slast[tid] = zr[tid];
    slast[tid + 64] = zr[tid + 64];
    __syncthreads();

    float acc = hb1[k*64 + tid];
    const float* w1 = hw1 + (size_t)k*DD*64;
    #pragma unroll 8
    for (int d = 0; d < DD; d++) acc += slast[d] * w1[d*64 + tid];
    sh1[tid] = fmaxf(acc, 0.f);
    __syncthreads();

    if (tid < 5) {
        float a2 = hb2[k*5 + tid];
        const float* w2 = hw2 + (size_t)k*64*5;
        #pragma unroll 8
        for (int m = 0; m < 64; m++) a2 += sh1[m] * w2[m*5 + tid];
        out[((size_t)k*BB + b)*5 + tid] = a2;
    }
}

// ---------------- launcher ----------------
extern "C" void kernel_launch(void* const* d_in, const int* in_sizes, int n_in,
                              void* d_out, int out_size)
{
    const float* x        = (const float*)d_in[0];
    const int*   ei       = (const int*)  d_in[1];
    const float* gcn_w    = (const float*)d_in[2];
    const float* gcn_b    = (const float*)d_in[3];
    const float* gat_w    = (const float*)d_in[4];
    const float* gat_a_s  = (const float*)d_in[5];
    const float* gat_a_d  = (const float*)d_in[6];
    const float* gat_b    = (const float*)d_in[7];
    const float* gln_g    = (const float*)d_in[8];
    const float* gln_b    = (const float*)d_in[9];
    const float* tw_qkv   = (const float*)d_in[10];
    const float* tb_qkv   = (const float*)d_in[11];
    const float* tw_o     = (const float*)d_in[12];
    const float* tb_o     = (const float*)d_in[13];
    const float* ln1_g    = (const float*)d_in[14];
    const float* ln1_b    = (const float*)d_in[15];
    const float* w_ff1    = (const float*)d_in[16];
    const float* b_ff1    = (const float*)d_in[17];
    const float* w_ff2    = (const float*)d_in[18];
    const float* b_ff2    = (const float*)d_in[19];
    const float* ln2_g    = (const float*)d_in[20];
    const float* ln2_b    = (const float*)d_in[21];
    const float* hw1      = (const float*)d_in[22];
    const float* hb1      = (const float*)d_in[23];
    const float* hw2      = (const float*)d_in[24];
    const float* hb2      = (const float*)d_in[25];
    float* out = (float*)d_out;

    float *zp, *qkvp;
    uint32_t *wtf, *ztf, *otf, *fftf;
    cudaGetSymbolAddress((void**)&zp,   d_z);
    cudaGetSymbolAddress((void**)&qkvp, d_qkv);
    cudaGetSymbolAddress((void**)&wtf,  d_wtf);
    cudaGetSymbolAddress((void**)&ztf,  d_ztf);
    cudaGetSymbolAddress((void**)&otf,  d_otf);
    cudaGetSymbolAddress((void**)&fftf, d_fftf);

    const int SMEM_PIPE = 4 * STAGE_WORDS * 4;    // 75776 B
    static bool attr_set = false;
    if (!attr_set) {
        cudaFuncSetAttribute(gemm_tf32<0>, cudaFuncAttributeMaxDynamicSharedMemorySize, SMEM_PIPE);
        cudaFuncSetAttribute(gemm_tf32<1>, cudaFuncAttributeMaxDynamicSharedMemorySize, SMEM_PIPE);
        cudaFuncSetAttribute(gemm_tf32<2>, cudaFuncAttributeMaxDynamicSharedMemorySize, SMEM_PIPE);
        attr_set = true;
    }

    int E = in_sizes[1] / 2;

    build_graph_kernel<<<1, 32>>>(ei, E);
    cvt_weights_kernel<<<192, 256>>>(tw_qkv, tw_o, w_ff1, w_ff2);

    gcn_gat_kernel<<<BT, 128>>>(x, gcn_w, gcn_b, gat_w, gat_a_s, gat_a_d,
                                gat_b, gln_g, gln_b, zp, ztf, E + NN);

    for (int i = 0; i < 3; i++) {
        gemm_tf32<0><<<dim3((3*DD)/128, BT/128), 256, SMEM_PIPE>>>(
            ztf, wtf + WOFF_QKV + (size_t)i*DD*3*DD, tb_qkv + (size_t)i*3*DD, qkvp,
            nullptr, nullptr, nullptr, nullptr, BT, 3*DD, DD);
        attn_kernel<<<dim3(BB, NHEAD), 256>>>(qkvp, otf);
        gemm_tf32<2><<<dim3(1, BT/128), 256, SMEM_PIPE>>>(
            otf, wtf + WOFF_O + (size_t)i*DD*DD, tb_o + (size_t)i*DD, zp,
            ztf, zp, ln1_g + (size_t)i*DD, ln1_b + (size_t)i*DD, BT, DD, DD);
        gemm_tf32<1><<<dim3(FFD/128, BT/128), 256, SMEM_PIPE>>>(
            ztf, wtf + WOFF_FF1 + (size_t)i*DD*FFD, b_ff1 + (size_t)i*FFD, nullptr,
            fftf, nullptr, nullptr, nullptr, BT, FFD, DD);
        gemm_tf32<2><<<dim3(1, BT/128), 256, SMEM_PIPE>>>(
            fftf, wtf + WOFF_FF2 + (size_t)i*FFD*DD, b_ff2 + (size_t)i*DD, zp,
            ztf, zp, ln2_g + (size_t)i*DD, ln2_b + (size_t)i*DD, BT, DD, FFD);
    }

    heads_kernel<<<dim3(BB, 6), 64>>>(zp, hw1, hb1, hw2, hb2, out);
}